// round 1
// baseline (speedup 1.0000x reference)
#include <cuda_runtime.h>
#include <math.h>

#define B_   2
#define S_   2048
#define D_   1024
#define H_   16
#define HD_  64
#define KJL  32
#define M_   (B_*S_)      // 4096 rows
#define QT   64           // queries per attention block

// ---- scratch (device globals: allocation is forbidden) --------------------
__device__ float g_qkv[B_*S_*3*D_];     // [B,S,3D]  ~50 MB
__device__ float g_qjl[B_*H_*S_*KJL];   // [B,H,S,K]
__device__ float g_kjl[B_*H_*S_*KJL];   // [B,H,S,K]
__device__ float g_ao [B_*S_*D_];       // merged attention output [B,S,D]

// ===========================================================================
// SGEMM + bias: C[M,N] = A[M,K] @ Bm[K,N] + bias[N]   (row-major, all dims
// divisible by tile sizes for this problem: M=4096, N in {3072,1024}, K=1024)
// 128x128 tile, BK=8, 256 threads, 8x8 per thread.
// ===========================================================================
__global__ __launch_bounds__(256)
void sgemm_bias(const float* __restrict__ A, const float* __restrict__ Bm,
                const float* __restrict__ bias, float* __restrict__ C,
                int M, int N, int K)
{
    const int BM = 128, BN = 128, BK = 8;
    __shared__ float As[BK][BM];
    __shared__ float Bs[BK][BN];

    const int tid  = threadIdx.x;
    const int brow = blockIdx.y * BM;
    const int bcol = blockIdx.x * BN;

    const int a_row = tid >> 1;          // 0..127
    const int a_col = (tid & 1) << 2;    // 0 or 4
    const int b_row = tid >> 5;          // 0..7
    const int b_col = (tid & 31) << 2;   // 0..124

    const int ty = (tid >> 4) << 3;      // 0..120 step 8
    const int tx = (tid & 15) << 3;

    float acc[8][8] = {};

    const float* Ap = A  + (long)(brow + a_row) * K + a_col;
    const float* Bp = Bm + (long)b_row * N + bcol + b_col;

    for (int k0 = 0; k0 < K; k0 += BK) {
        float4 av = *(const float4*)(Ap + k0);
        As[a_col + 0][a_row] = av.x;
        As[a_col + 1][a_row] = av.y;
        As[a_col + 2][a_row] = av.z;
        As[a_col + 3][a_row] = av.w;
        *(float4*)&Bs[b_row][b_col] = *(const float4*)(Bp + (long)k0 * N);
        __syncthreads();

        #pragma unroll
        for (int kk = 0; kk < BK; kk++) {
            float ar[8], br[8];
            #pragma unroll
            for (int i = 0; i < 8; i++) ar[i] = As[kk][ty + i];
            #pragma unroll
            for (int j = 0; j < 8; j++) br[j] = Bs[kk][tx + j];
            #pragma unroll
            for (int i = 0; i < 8; i++)
                #pragma unroll
                for (int j = 0; j < 8; j++)
                    acc[i][j] += ar[i] * br[j];
        }
        __syncthreads();
    }

    #pragma unroll
    for (int i = 0; i < 8; i++) {
        float* Cp = C + (long)(brow + ty + i) * N + bcol + tx;
        #pragma unroll
        for (int j = 0; j < 8; j += 4) {
            float4 o;
            o.x = acc[i][j + 0] + bias[bcol + tx + j + 0];
            o.y = acc[i][j + 1] + bias[bcol + tx + j + 1];
            o.z = acc[i][j + 2] + bias[bcol + tx + j + 2];
            o.w = acc[i][j + 3] + bias[bcol + tx + j + 3];
            *(float4*)(Cp + j) = o;
        }
    }
}

// ===========================================================================
// JL projection: out[b,h,s,k] = sum_d qkv[b,s, which*D + h*64 + d] * Sp[k,d]
// grid = (S/128, B*H, 2 {q,k}), block = 128
// ===========================================================================
__global__ __launch_bounds__(128)
void jl_project(const float* __restrict__ qkv, const float* __restrict__ Sp,
                float* __restrict__ qjl, float* __restrict__ kjl)
{
    __shared__ float sp[KJL][HD_];
    const int tid = threadIdx.x;
    for (int i = tid; i < KJL * HD_; i += 128)
        sp[i / HD_][i % HD_] = Sp[i];
    __syncthreads();

    const int s  = blockIdx.x * 128 + tid;
    const int bh = blockIdx.y;
    const int b  = bh >> 4, h = bh & 15;
    const int which = blockIdx.z;          // 0 = q, 1 = k

    const float* row = qkv + ((long)(b * S_ + s)) * (3 * D_) + which * D_ + h * HD_;
    float x[HD_];
    #pragma unroll
    for (int i = 0; i < HD_ / 4; i++) {
        float4 v = *(const float4*)(row + i * 4);
        x[4*i+0] = v.x; x[4*i+1] = v.y; x[4*i+2] = v.z; x[4*i+3] = v.w;
    }

    float* out = (which == 0 ? qjl : kjl) + ((long)bh * S_ + s) * KJL;
    #pragma unroll
    for (int k = 0; k < KJL; k++) {
        float a = 0.f;
        #pragma unroll
        for (int d = 0; d < HD_; d++) a += x[d] * sp[k][d];
        out[k] = a;
    }
}

// ===========================================================================
// Causal flash attention. 1 thread = 1 query. K_JL=32 scores, HD=64 values.
// grid = (S/QT, H, B), block = QT=64
// ===========================================================================
__global__ __launch_bounds__(QT)
void attn_kernel(const float* __restrict__ qjl, const float* __restrict__ kjl,
                 const float* __restrict__ qkv, float* __restrict__ ao)
{
    __shared__ float Ks[QT][KJL];
    __shared__ float Vs[QT][HD_];

    const int tid = threadIdx.x;
    const int qt  = blockIdx.x;
    const int h   = blockIdx.y;
    const int b   = blockIdx.z;
    const int bh  = b * H_ + h;
    const int qi  = qt * QT + tid;

    // load q row
    const float* qrow = qjl + ((long)bh * S_ + qi) * KJL;
    float q[KJL];
    #pragma unroll
    for (int i = 0; i < KJL / 4; i++) {
        float4 v = *(const float4*)(qrow + i * 4);
        q[4*i+0] = v.x; q[4*i+1] = v.y; q[4*i+2] = v.z; q[4*i+3] = v.w;
    }

    float acc[HD_];
    #pragma unroll
    for (int d = 0; d < HD_; d++) acc[d] = 0.f;
    float m = -1e30f, l = 0.f;

    for (int kt = 0; kt <= qt; kt++) {
        // K tile: contiguous QT*KJL floats
        {
            const float4* ksrc = (const float4*)(kjl + ((long)bh * S_ + kt * QT) * KJL);
            float4* kdst = (float4*)&Ks[0][0];
            #pragma unroll
            for (int i = 0; i < (QT * KJL / 4) / QT; i++)
                kdst[tid + i * QT] = ksrc[tid + i * QT];
        }
        // V tile: rows strided by 3D in qkv
        #pragma unroll
        for (int it = 0; it < (QT * HD_ / 4) / QT; it++) {
            int i = tid + it * QT;
            int r = i >> 4;            // /16 float4 per row
            int c = i & 15;
            ((float4*)&Vs[r][0])[c] =
                *(const float4*)(qkv + ((long)(b * S_ + kt * QT + r)) * (3 * D_)
                                 + 2 * D_ + h * HD_ + c * 4);
        }
        __syncthreads();

        const int jmax = (kt < qt) ? QT : (tid + 1);
        for (int j = 0; j < jmax; j++) {
            float s = 0.f;
            #pragma unroll
            for (int d = 0; d < KJL; d++) s += q[d] * Ks[j][d];
            s *= 0.125f;                       // 1/sqrt(HD)
            float nm    = fmaxf(m, s);
            float scale = __expf(m - nm);
            float p     = __expf(s - nm);
            l = l * scale + p;
            #pragma unroll
            for (int d = 0; d < HD_; d++)
                acc[d] = acc[d] * scale + p * Vs[j][d];
            m = nm;
        }
        __syncthreads();
    }

    const float inv = 1.f / l;
    float* orow = ao + ((long)(b * S_ + qi)) * D_ + h * HD_;
    #pragma unroll
    for (int d = 0; d < HD_; d += 4) {
        float4 o;
        o.x = acc[d+0] * inv; o.y = acc[d+1] * inv;
        o.z = acc[d+2] * inv; o.w = acc[d+3] * inv;
        *(float4*)(orow + d) = o;
    }
}

// ===========================================================================
extern "C" void kernel_launch(void* const* d_in, const int* in_sizes, int n_in,
                              void* d_out, int out_size)
{
    const float* X    = (const float*)d_in[0];  // [B,S,D]
    const float* Wat  = (const float*)d_in[1];  // [D,3D]
    const float* bat  = (const float*)d_in[2];  // [3D]
    const float* Sp   = (const float*)d_in[3];  // [K,HD]
    const float* Wp   = (const float*)d_in[4];  // [D,D]
    const float* bp   = (const float*)d_in[5];  // [D]
    float* out = (float*)d_out;                 // [B,S,D]

    float *qkv, *qjl, *kjl, *ao;
    cudaGetSymbolAddress((void**)&qkv, g_qkv);
    cudaGetSymbolAddress((void**)&qjl, g_qjl);
    cudaGetSymbolAddress((void**)&kjl, g_kjl);
    cudaGetSymbolAddress((void**)&ao,  g_ao);

    // 1. QKV = X @ W_attn + b_attn
    dim3 g1(3 * D_ / 128, M_ / 128);
    sgemm_bias<<<g1, 256>>>(X, Wat, bat, qkv, M_, 3 * D_, D_);

    // 2. JL projection of q and k
    dim3 g2(S_ / 128, B_ * H_, 2);
    jl_project<<<g2, 128>>>(qkv, Sp, qjl, kjl);

    // 3. causal flash attention -> merged [B,S,D]
    dim3 g3(S_ / QT, H_, B_);
    attn_kernel<<<g3, QT>>>(qjl, kjl, qkv, ao);

    // 4. out = ao @ W_proj + b_proj
    dim3 g4(D_ / 128, M_ / 128);
    sgemm_bias<<<g4, 256>>>(ao, Wp, bp, out, M_, D_, D_);
}

// round 2
// speedup vs baseline: 1.6082x; 1.6082x over previous
#include <cuda_runtime.h>
#include <math.h>

#define B_   2
#define S_   2048
#define D_   1024
#define H_   16
#define HD_  64
#define KJL  32
#define M_   (B_*S_)      // 4096 rows
#define NF   2048         // folded qkv width: 512 qjl | 512 kjl | 1024 v
#define KT   64           // key tile

// ---- scratch (device globals: allocation is forbidden) --------------------
__device__ float g_wf[D_*NF];        // folded weights [D, 2048]
__device__ float g_bf[NF];           // folded bias
__device__ float g_x2[M_*NF];        // folded qkv output [B*S, 2048]
__device__ float g_ao[M_*D_];        // merged attention output [B,S,D]

// ===========================================================================
// Fold weights: Wf[d, h*32+k]       = sum_e Wat[d, h*64+e]      * Sp[k,e]
//               Wf[d, 512+h*32+k]   = sum_e Wat[d, 1024+h*64+e] * Sp[k,e]
//               Wf[d, 1024+c]       = Wat[d, 2048+c]
// grid = D_ blocks, 256 threads
// ===========================================================================
__global__ __launch_bounds__(256)
void fold_weights(const float* __restrict__ Wat, const float* __restrict__ Sp,
                  float* __restrict__ Wf)
{
    __shared__ float w[2048];          // q & k chunks of this W row
    __shared__ float sp[KJL][HD_];
    const int d = blockIdx.x, tid = threadIdx.x;
    for (int i = tid; i < 2048; i += 256) w[i] = Wat[(long)d * (3*D_) + i];
    for (int i = tid; i < KJL*HD_; i += 256) sp[i >> 6][i & 63] = Sp[i];
    __syncthreads();

    for (int o = tid; o < 1024; o += 256) {
        const int part = o >> 9;             // 0=q, 1=k
        const int hk = o & 511, h = hk >> 5, k = hk & 31;
        const float* src = w + part * 1024 + h * HD_;
        float a = 0.f;
        #pragma unroll
        for (int e = 0; e < HD_; e++) a += src[e] * sp[k][e];
        Wf[(long)d * NF + part * 512 + hk] = a;
    }
    for (int i = tid; i < 1024; i += 256)
        Wf[(long)d * NF + 1024 + i] = Wat[(long)d * (3*D_) + 2048 + i];
}

__global__ void fold_bias(const float* __restrict__ bat,
                          const float* __restrict__ Sp, float* __restrict__ bf)
{
    const int i = blockIdx.x * 256 + threadIdx.x;
    if (i >= NF) return;
    if (i < 1024) {
        const int part = i >> 9, hk = i & 511, h = hk >> 5, k = hk & 31;
        float a = 0.f;
        #pragma unroll
        for (int e = 0; e < HD_; e++) a += bat[part*1024 + h*HD_ + e] * Sp[k*HD_ + e];
        bf[i] = a;
    } else {
        bf[i] = bat[2048 + (i - 1024)];
    }
}

// ===========================================================================
// Double-buffered SGEMM + bias: C[M,N] = A[M,K] @ Bm[K,N] + bias[N]
// 128x128 tile, BK=8, 256 threads, 8x8 per thread, 2-stage smem pipeline.
// ===========================================================================
__global__ __launch_bounds__(256)
void sgemm_bias(const float* __restrict__ A, const float* __restrict__ Bm,
                const float* __restrict__ bias, float* __restrict__ C,
                int M, int N, int K)
{
    const int BM = 128, BN = 128, BK = 8;
    __shared__ float As[2][BK][BM];
    __shared__ float Bs[2][BK][BN];

    const int tid  = threadIdx.x;
    const int brow = blockIdx.y * BM;
    const int bcol = blockIdx.x * BN;

    const int a_row = tid >> 1;          // 0..127
    const int a_col = (tid & 1) << 2;    // 0 or 4
    const int b_row = tid >> 5;          // 0..7
    const int b_col = (tid & 31) << 2;   // 0..124

    const int ty = (tid >> 4) << 3;
    const int tx = (tid & 15) << 3;

    float acc[8][8] = {};

    const float* Ap = A  + (long)(brow + a_row) * K + a_col;
    const float* Bp = Bm + (long)b_row * N + bcol + b_col;

    float4 av = *(const float4*)(Ap);
    float4 bv = *(const float4*)(Bp);
    As[0][a_col+0][a_row] = av.x;
    As[0][a_col+1][a_row] = av.y;
    As[0][a_col+2][a_row] = av.z;
    As[0][a_col+3][a_row] = av.w;
    *(float4*)&Bs[0][b_row][b_col] = bv;
    __syncthreads();

    int buf = 0;
    for (int k0 = 0; k0 < K; k0 += BK) {
        const bool more = (k0 + BK) < K;
        if (more) {
            av = *(const float4*)(Ap + k0 + BK);
            bv = *(const float4*)(Bp + (long)(k0 + BK) * N);
        }
        #pragma unroll
        for (int kk = 0; kk < BK; kk++) {
            float ar[8], br[8];
            #pragma unroll
            for (int i = 0; i < 8; i++) ar[i] = As[buf][kk][ty + i];
            #pragma unroll
            for (int j = 0; j < 8; j++) br[j] = Bs[buf][kk][tx + j];
            #pragma unroll
            for (int i = 0; i < 8; i++)
                #pragma unroll
                for (int j = 0; j < 8; j++)
                    acc[i][j] += ar[i] * br[j];
        }
        if (more) {
            As[buf^1][a_col+0][a_row] = av.x;
            As[buf^1][a_col+1][a_row] = av.y;
            As[buf^1][a_col+2][a_row] = av.z;
            As[buf^1][a_col+3][a_row] = av.w;
            *(float4*)&Bs[buf^1][b_row][b_col] = bv;
        }
        __syncthreads();
        buf ^= 1;
    }

    #pragma unroll
    for (int i = 0; i < 8; i++) {
        float* Cp = C + (long)(brow + ty + i) * N + bcol + tx;
        #pragma unroll
        for (int j = 0; j < 8; j += 4) {
            float4 o;
            o.x = acc[i][j+0] + bias[bcol + tx + j + 0];
            o.y = acc[i][j+1] + bias[bcol + tx + j + 1];
            o.z = acc[i][j+2] + bias[bcol + tx + j + 2];
            o.w = acc[i][j+3] + bias[bcol + tx + j + 3];
            *(float4*)(Cp + j) = o;
        }
    }
}

// ===========================================================================
// Causal flash attention on folded layout. 1 thread = 1 query, 128 q/block.
// q_jl at x2[row, h*32], k_jl at x2[row, 512+h*32], v at x2[row, 1024+h*64].
// 16-key subtiles with tile-level online-softmax rescale.
// grid = (S/128, H, B), block = 128
// ===========================================================================
__global__ __launch_bounds__(128)
void attn_kernel(const float* __restrict__ x2, float* __restrict__ ao)
{
    __shared__ float Ks[KT][KJL];
    __shared__ float Vs[KT][HD_];

    const int tid = threadIdx.x;
    const int h   = blockIdx.y;
    const int b   = blockIdx.z;
    const int q0  = blockIdx.x * 128;
    const int qi  = q0 + tid;

    const float* qrow = x2 + (long)(b * S_ + qi) * NF + h * KJL;
    float q[KJL];
    #pragma unroll
    for (int i = 0; i < KJL/4; i++) {
        float4 v = *(const float4*)(qrow + i * 4);
        q[4*i+0] = v.x; q[4*i+1] = v.y; q[4*i+2] = v.z; q[4*i+3] = v.w;
    }

    float acc[HD_];
    #pragma unroll
    for (int d = 0; d < HD_; d++) acc[d] = 0.f;
    float m = -1e30f, l = 0.f;

    const int nkt = (q0 + 128) / KT;      // tiles covering all queries in block
    for (int kt = 0; kt < nkt; kt++) {
        // K tile: 64 rows x 32 floats = 512 float4
        {
            const float* kbase = x2 + (long)(b * S_ + kt * KT) * NF + 512 + h * KJL;
            #pragma unroll
            for (int t = 0; t < 4; t++) {
                int idx = tid + t * 128;
                int r = idx >> 3, c = idx & 7;
                ((float4*)&Ks[r][0])[c] = *(const float4*)(kbase + (long)r * NF + c * 4);
            }
        }
        // V tile: 64 rows x 64 floats = 1024 float4
        {
            const float* vbase = x2 + (long)(b * S_ + kt * KT) * NF + 1024 + h * HD_;
            #pragma unroll
            for (int t = 0; t < 8; t++) {
                int idx = tid + t * 128;
                int r = idx >> 4, c = idx & 15;
                ((float4*)&Vs[r][0])[c] = *(const float4*)(vbase + (long)r * NF + c * 4);
            }
        }
        __syncthreads();

        if (kt * KT <= qi) {
            #pragma unroll
            for (int sub = 0; sub < 4; sub++) {
                const int jbase = kt * KT + sub * 16;
                if (jbase > qi) break;
                float s[16];
                #pragma unroll
                for (int jj = 0; jj < 16; jj++) {
                    float a = 0.f;
                    #pragma unroll
                    for (int d = 0; d < KJL; d++) a += q[d] * Ks[sub*16 + jj][d];
                    s[jj] = (jbase + jj <= qi) ? a * 0.125f : -1e30f;
                }
                float tmax = -1e30f;
                #pragma unroll
                for (int jj = 0; jj < 16; jj++) tmax = fmaxf(tmax, s[jj]);
                const float nm    = fmaxf(m, tmax);
                const float scale = __expf(m - nm);
                float ps = 0.f;
                #pragma unroll
                for (int jj = 0; jj < 16; jj++) {
                    s[jj] = __expf(s[jj] - nm);
                    ps += s[jj];
                }
                l = l * scale + ps;
                #pragma unroll
                for (int d = 0; d < HD_; d++) acc[d] *= scale;
                #pragma unroll
                for (int jj = 0; jj < 16; jj++)
                    #pragma unroll
                    for (int d = 0; d < HD_; d++)
                        acc[d] += s[jj] * Vs[sub*16 + jj][d];
                m = nm;
            }
        }
        __syncthreads();
    }

    const float inv = 1.f / l;
    float* orow = ao + (long)(b * S_ + qi) * D_ + h * HD_;
    #pragma unroll
    for (int d = 0; d < HD_; d += 4) {
        float4 o;
        o.x = acc[d+0] * inv; o.y = acc[d+1] * inv;
        o.z = acc[d+2] * inv; o.w = acc[d+3] * inv;
        *(float4*)(orow + d) = o;
    }
}

// ===========================================================================
extern "C" void kernel_launch(void* const* d_in, const int* in_sizes, int n_in,
                              void* d_out, int out_size)
{
    const float* X    = (const float*)d_in[0];  // [B,S,D]
    const float* Wat  = (const float*)d_in[1];  // [D,3D]
    const float* bat  = (const float*)d_in[2];  // [3D]
    const float* Sp   = (const float*)d_in[3];  // [K,HD]
    const float* Wp   = (const float*)d_in[4];  // [D,D]
    const float* bp   = (const float*)d_in[5];  // [D]
    float* out = (float*)d_out;                 // [B,S,D]

    float *wf, *bf, *x2, *ao;
    cudaGetSymbolAddress((void**)&wf, g_wf);
    cudaGetSymbolAddress((void**)&bf, g_bf);
    cudaGetSymbolAddress((void**)&x2, g_x2);
    cudaGetSymbolAddress((void**)&ao, g_ao);

    // 0. fold S_proj into attention weights/bias
    fold_weights<<<D_, 256>>>(Wat, Sp, wf);
    fold_bias<<<NF/256, 256>>>(bat, Sp, bf);

    // 1. folded QKV: x2 = X @ Wf + bf   [4096, 2048]
    dim3 g1(NF/128, M_/128);
    sgemm_bias<<<g1, 256>>>(X, wf, bf, x2, M_, NF, D_);

    // 2. causal flash attention -> merged [B,S,D]
    dim3 g3(S_/128, H_, B_);
    attn_kernel<<<g3, 128>>>(x2, ao);

    // 3. out = ao @ W_proj + b_proj
    dim3 g4(D_/128, M_/128);
    sgemm_bias<<<g4, 256>>>(ao, Wp, bp, out, M_, D_, D_);
}

// round 3
// speedup vs baseline: 1.9062x; 1.1853x over previous
#include <cuda_runtime.h>
#include <mma.h>
#include <math.h>

using namespace nvcuda;

#define B_   2
#define S_   2048
#define D_   1024
#define H_   16
#define HD_  64
#define KJL  32
#define M_   (B_*S_)      // 4096 rows
#define NF   2048         // folded qkv width: 512 qjl | 512 kjl | 1024 v
#define KT   64           // key tile

// ---- scratch (device globals: allocation is forbidden) --------------------
__device__ float g_wf[D_*NF];        // folded weights [D, 2048]
__device__ float g_bf[NF];           // folded bias
__device__ float g_x2[M_*NF];        // folded qkv output [B*S, 2048]
__device__ float g_ao[M_*D_];        // merged attention output [B,S,D]

// ===========================================================================
// Fold weights: Wf[d, h*32+k]     = sum_e Wat[d, h*64+e]      * Sp[k,e]
//               Wf[d, 512+h*32+k] = sum_e Wat[d, 1024+h*64+e] * Sp[k,e]
//               Wf[d, 1024+c]     = Wat[d, 2048+c]
// ===========================================================================
__global__ __launch_bounds__(256)
void fold_weights(const float* __restrict__ Wat, const float* __restrict__ Sp,
                  float* __restrict__ Wf)
{
    __shared__ float w[2048];
    __shared__ float sp[KJL][HD_];
    const int d = blockIdx.x, tid = threadIdx.x;
    for (int i = tid; i < 2048; i += 256) w[i] = Wat[(long)d * (3*D_) + i];
    for (int i = tid; i < KJL*HD_; i += 256) sp[i >> 6][i & 63] = Sp[i];
    __syncthreads();

    for (int o = tid; o < 1024; o += 256) {
        const int part = o >> 9;
        const int hk = o & 511, h = hk >> 5, k = hk & 31;
        const float* src = w + part * 1024 + h * HD_;
        float a = 0.f;
        #pragma unroll
        for (int e = 0; e < HD_; e++) a += src[e] * sp[k][e];
        Wf[(long)d * NF + part * 512 + hk] = a;
    }
    for (int i = tid; i < 1024; i += 256)
        Wf[(long)d * NF + 1024 + i] = Wat[(long)d * (3*D_) + 2048 + i];
}

__global__ void fold_bias(const float* __restrict__ bat,
                          const float* __restrict__ Sp, float* __restrict__ bf)
{
    const int i = blockIdx.x * 256 + threadIdx.x;
    if (i >= NF) return;
    if (i < 1024) {
        const int part = i >> 9, hk = i & 511, h = hk >> 5, k = hk & 31;
        float a = 0.f;
        #pragma unroll
        for (int e = 0; e < HD_; e++) a += bat[part*1024 + h*HD_ + e] * Sp[k*HD_ + e];
        bf[i] = a;
    } else {
        bf[i] = bat[2048 + (i - 1024)];
    }
}

// ===========================================================================
// TF32 tensor-core GEMM + bias: C[M,N] = A[M,K] @ Bm[K,N] + bias[N]
// 128x128x16 block tile, 256 threads = 8 warps in 4(m) x 2(n),
// warp tile 32x64 = 2x4 wmma(16x16x8) tiles. Double-buffered smem.
// Bias folded into accumulator init (acc frag loaded from broadcast tile).
// M,N,K all divisible by tile dims for this problem.
// ===========================================================================
#define GBM 128
#define GBN 128
#define GBK 16
#define LDA 20     // As leading dim (pad)
#define LDB 132    // Bs leading dim (pad)

__global__ __launch_bounds__(256)
void tf32_gemm_bias(const float* __restrict__ A, const float* __restrict__ Bm,
                    const float* __restrict__ bias, float* __restrict__ C,
                    int M, int N, int K)
{
    __shared__ float As[2][GBM][LDA];
    __shared__ float Bs[2][GBK][LDB];
    __shared__ float biasS[16][LDB];

    const int tid  = threadIdx.x;
    const int wid  = tid >> 5;
    const int brow = blockIdx.y * GBM;
    const int bcol = blockIdx.x * GBN;
    const int wm   = (wid & 3) * 32;    // warp row offset in tile
    const int wn   = (wid >> 2) * 64;   // warp col offset in tile

    // bias broadcast tile: 16 identical rows
    for (int t = 0; t < 8; t++) {
        int idx = tid + t * 256;
        biasS[idx >> 7][idx & 127] = bias[bcol + (idx & 127)];
    }
    __syncthreads();

    wmma::fragment<wmma::accumulator, 16, 16, 8, float> acc[2][4];
    #pragma unroll
    for (int i = 0; i < 2; i++)
        #pragma unroll
        for (int j = 0; j < 4; j++)
            wmma::load_matrix_sync(acc[i][j], &biasS[0][wn + j*16], LDB,
                                   wmma::mem_row_major);

    // global load indexing (per chunk: A 128x16, B 16x128, 2 float4/thread each)
    const int ar0 = tid >> 2,  ac0 = (tid & 3) << 2;   // + idx 256 -> row +64
    const int br0 = tid >> 5,  bc0 = (tid & 31) << 2;  // + idx 256 -> row +8

    const float* Ap0 = A  + (long)(brow + ar0) * K + ac0;
    const float* Ap1 = A  + (long)(brow + ar0 + 64) * K + ac0;
    const float* Bp0 = Bm + (long)br0 * N + bcol + bc0;
    const float* Bp1 = Bm + (long)(br0 + 8) * N + bcol + bc0;

    // preload chunk 0
    {
        float4 a0 = *(const float4*)Ap0;
        float4 a1 = *(const float4*)Ap1;
        float4 b0 = *(const float4*)Bp0;
        float4 b1 = *(const float4*)Bp1;
        *(float4*)&As[0][ar0][ac0]      = a0;
        *(float4*)&As[0][ar0 + 64][ac0] = a1;
        *(float4*)&Bs[0][br0][bc0]      = b0;
        *(float4*)&Bs[0][br0 + 8][bc0]  = b1;
    }
    __syncthreads();

    int buf = 0;
    for (int k0 = 0; k0 < K; k0 += GBK) {
        float4 a0, a1, b0, b1;
        const bool more = (k0 + GBK) < K;
        if (more) {
            a0 = *(const float4*)(Ap0 + k0 + GBK);
            a1 = *(const float4*)(Ap1 + k0 + GBK);
            b0 = *(const float4*)(Bp0 + (long)(k0 + GBK) * N);
            b1 = *(const float4*)(Bp1 + (long)(k0 + GBK) * N);
        }

        #pragma unroll
        for (int kk = 0; kk < GBK; kk += 8) {
            wmma::fragment<wmma::matrix_a, 16, 16, 8, wmma::precision::tf32,
                           wmma::row_major> a_frag[2];
            wmma::fragment<wmma::matrix_b, 16, 16, 8, wmma::precision::tf32,
                           wmma::row_major> b_frag[4];
            #pragma unroll
            for (int i = 0; i < 2; i++) {
                wmma::load_matrix_sync(a_frag[i], &As[buf][wm + i*16][kk], LDA);
                #pragma unroll
                for (int e = 0; e < a_frag[i].num_elements; e++)
                    a_frag[i].x[e] = wmma::__float_to_tf32(a_frag[i].x[e]);
            }
            #pragma unroll
            for (int j = 0; j < 4; j++) {
                wmma::load_matrix_sync(b_frag[j], &Bs[buf][kk][wn + j*16], LDB);
                #pragma unroll
                for (int e = 0; e < b_frag[j].num_elements; e++)
                    b_frag[j].x[e] = wmma::__float_to_tf32(b_frag[j].x[e]);
            }
            #pragma unroll
            for (int i = 0; i < 2; i++)
                #pragma unroll
                for (int j = 0; j < 4; j++)
                    wmma::mma_sync(acc[i][j], a_frag[i], b_frag[j], acc[i][j]);
        }

        if (more) {
            *(float4*)&As[buf^1][ar0][ac0]      = a0;
            *(float4*)&As[buf^1][ar0 + 64][ac0] = a1;
            *(float4*)&Bs[buf^1][br0][bc0]      = b0;
            *(float4*)&Bs[buf^1][br0 + 8][bc0]  = b1;
        }
        __syncthreads();
        buf ^= 1;
    }

    #pragma unroll
    for (int i = 0; i < 2; i++)
        #pragma unroll
        for (int j = 0; j < 4; j++)
            wmma::store_matrix_sync(
                C + (long)(brow + wm + i*16) * N + bcol + wn + j*16,
                acc[i][j], N, wmma::mem_row_major);
}

// ===========================================================================
// Causal flash attention on folded layout.
// block = 256 threads: 128 queries x 2 HD-halves. Thread (q_local, half)
// owns acc over d in [half*32, half*32+32); scores computed redundantly.
// q_jl at x2[row, h*32], k_jl at x2[row, 512+h*32], v at x2[row, 1024+h*64].
// grid = (S/128, H, B)
// ===========================================================================
__global__ __launch_bounds__(256)
void attn_kernel(const float* __restrict__ x2, float* __restrict__ ao)
{
    __shared__ float Ks[KT][KJL];
    __shared__ float Vs[KT][HD_];

    const int tid = threadIdx.x;
    const int ql  = tid >> 1;          // 0..127
    const int hf  = (tid & 1) * 32;    // HD half offset
    const int h   = blockIdx.y;
    const int b   = blockIdx.z;
    const int q0  = blockIdx.x * 128;
    const int qi  = q0 + ql;

    const float* qrow = x2 + (long)(b * S_ + qi) * NF + h * KJL;
    float q[KJL];
    #pragma unroll
    for (int i = 0; i < KJL/4; i++) {
        float4 v = *(const float4*)(qrow + i * 4);
        q[4*i+0] = v.x; q[4*i+1] = v.y; q[4*i+2] = v.z; q[4*i+3] = v.w;
    }

    float acc[32];
    #pragma unroll
    for (int d = 0; d < 32; d++) acc[d] = 0.f;
    float m = -1e30f, l = 0.f;

    const int nkt = (q0 + 128) / KT;
    for (int kt = 0; kt < nkt; kt++) {
        // K tile: 64 rows x 8 float4 = 512 float4, 256 threads x 2
        {
            const float* kbase = x2 + (long)(b * S_ + kt * KT) * NF + 512 + h * KJL;
            #pragma unroll
            for (int t = 0; t < 2; t++) {
                int idx = tid + t * 256;
                int r = idx >> 3, c = idx & 7;
                ((float4*)&Ks[r][0])[c] = *(const float4*)(kbase + (long)r * NF + c * 4);
            }
        }
        // V tile: 64 rows x 16 float4 = 1024 float4, 256 threads x 4
        {
            const float* vbase = x2 + (long)(b * S_ + kt * KT) * NF + 1024 + h * HD_;
            #pragma unroll
            for (int t = 0; t < 4; t++) {
                int idx = tid + t * 256;
                int r = idx >> 4, c = idx & 15;
                ((float4*)&Vs[r][0])[c] = *(const float4*)(vbase + (long)r * NF + c * 4);
            }
        }
        __syncthreads();

        if (kt * KT <= qi) {
            #pragma unroll
            for (int sub = 0; sub < 4; sub++) {
                const int jbase = kt * KT + sub * 16;
                if (jbase > qi) break;
                float s[16];
                #pragma unroll
                for (int jj = 0; jj < 16; jj++) {
                    float a = 0.f;
                    #pragma unroll
                    for (int d = 0; d < KJL; d++) a += q[d] * Ks[sub*16 + jj][d];
                    s[jj] = (jbase + jj <= qi) ? a * 0.125f : -1e30f;
                }
                float tmax = -1e30f;
                #pragma unroll
                for (int jj = 0; jj < 16; jj++) tmax = fmaxf(tmax, s[jj]);
                const float nm    = fmaxf(m, tmax);
                const float scale = __expf(m - nm);
                float ps = 0.f;
                #pragma unroll
                for (int jj = 0; jj < 16; jj++) {
                    s[jj] = __expf(s[jj] - nm);
                    ps += s[jj];
                }
                l = l * scale + ps;
                #pragma unroll
                for (int d = 0; d < 32; d++) acc[d] *= scale;
                #pragma unroll
                for (int jj = 0; jj < 16; jj++)
                    #pragma unroll
                    for (int d = 0; d < 32; d++)
                        acc[d] += s[jj] * Vs[sub*16 + jj][hf + d];
                m = nm;
            }
        }
        __syncthreads();
    }

    const float inv = 1.f / l;
    float* orow = ao + (long)(b * S_ + qi) * D_ + h * HD_ + hf;
    #pragma unroll
    for (int d = 0; d < 32; d += 4) {
        float4 o;
        o.x = acc[d+0] * inv; o.y = acc[d+1] * inv;
        o.z = acc[d+2] * inv; o.w = acc[d+3] * inv;
        *(float4*)(orow + d) = o;
    }
}

// ===========================================================================
extern "C" void kernel_launch(void* const* d_in, const int* in_sizes, int n_in,
                              void* d_out, int out_size)
{
    const float* X    = (const float*)d_in[0];  // [B,S,D]
    const float* Wat  = (const float*)d_in[1];  // [D,3D]
    const float* bat  = (const float*)d_in[2];  // [3D]
    const float* Sp   = (const float*)d_in[3];  // [K,HD]
    const float* Wp   = (const float*)d_in[4];  // [D,D]
    const float* bp   = (const float*)d_in[5];  // [D]
    float* out = (float*)d_out;                 // [B,S,D]

    float *wf, *bf, *x2, *ao;
    cudaGetSymbolAddress((void**)&wf, g_wf);
    cudaGetSymbolAddress((void**)&bf, g_bf);
    cudaGetSymbolAddress((void**)&x2, g_x2);
    cudaGetSymbolAddress((void**)&ao, g_ao);

    // 0. fold S_proj into attention weights/bias
    fold_weights<<<D_, 256>>>(Wat, Sp, wf);
    fold_bias<<<NF/256, 256>>>(bat, Sp, bf);

    // 1. folded QKV: x2 = X @ Wf + bf   [4096, 2048]
    dim3 g1(NF/GBN, M_/GBM);
    tf32_gemm_bias<<<g1, 256>>>(X, wf, bf, x2, M_, NF, D_);

    // 2. causal flash attention -> merged [B,S,D]
    dim3 g3(S_/128, H_, B_);
    attn_kernel<<<g3, 256>>>(x2, ao);

    // 3. out = ao @ W_proj + b_proj
    dim3 g4(D_/GBN, M_/GBM);
    tf32_gemm_bias<<<g4, 256>>>(ao, Wp, bp, out, M_, D_, D_);
}

// round 4
// speedup vs baseline: 4.1916x; 2.1990x over previous
#include <cuda_runtime.h>
#include <mma.h>
#include <math.h>
#include <stdint.h>

using namespace nvcuda;

#define B_   2
#define S_   2048
#define D_   1024
#define H_   16
#define HD_  64
#define KJL  32
#define M_   (B_*S_)
#define NF   2048         // folded qkv width: 512 qjl | 512 kjl | 1024 v

// ---- scratch (device globals: allocation is forbidden) --------------------
__device__ float g_wf[D_*NF];
__device__ float g_bf[NF];
__device__ float g_x2[M_*NF];
__device__ float g_ao[M_*D_];

__device__ __forceinline__ float rtf32(float x) {
    asm("cvt.rna.tf32.f32 %0, %1;" : "=f"(x) : "f"(x));
    return x;
}

// ===========================================================================
// Fold S_proj into attention weights / bias (exact linear algebra)
// ===========================================================================
__global__ __launch_bounds__(256)
void fold_weights(const float* __restrict__ Wat, const float* __restrict__ Sp,
                  float* __restrict__ Wf)
{
    __shared__ float w[2048];
    __shared__ float sp[KJL][HD_];
    const int d = blockIdx.x, tid = threadIdx.x;
    for (int i = tid; i < 2048; i += 256) w[i] = Wat[(long)d * (3*D_) + i];
    for (int i = tid; i < KJL*HD_; i += 256) sp[i >> 6][i & 63] = Sp[i];
    __syncthreads();

    for (int o = tid; o < 1024; o += 256) {
        const int part = o >> 9;
        const int hk = o & 511, h = hk >> 5, k = hk & 31;
        const float* src = w + part * 1024 + h * HD_;
        float a = 0.f;
        #pragma unroll
        for (int e = 0; e < HD_; e++) a += src[e] * sp[k][e];
        Wf[(long)d * NF + part * 512 + hk] = a;
    }
    for (int i = tid; i < 1024; i += 256)
        Wf[(long)d * NF + 1024 + i] = Wat[(long)d * (3*D_) + 2048 + i];
}

__global__ void fold_bias(const float* __restrict__ bat,
                          const float* __restrict__ Sp, float* __restrict__ bf)
{
    const int i = blockIdx.x * 256 + threadIdx.x;
    if (i >= NF) return;
    if (i < 1024) {
        const int part = i >> 9, hk = i & 511, h = hk >> 5, k = hk & 31;
        float a = 0.f;
        #pragma unroll
        for (int e = 0; e < HD_; e++) a += bat[part*1024 + h*HD_ + e] * Sp[k*HD_ + e];
        bf[i] = a;
    } else {
        bf[i] = bat[2048 + (i - 1024)];
    }
}

// ===========================================================================
// TF32 tensor-core GEMM + bias (wmma). Inputs tf32-rounded at smem store;
// no per-fragment conversion in the hot loop.
// ===========================================================================
#define GBM 128
#define GBN 128
#define GBK 16
#define LDA 20
#define LDB 132

__global__ __launch_bounds__(256)
void tf32_gemm_bias(const float* __restrict__ A, const float* __restrict__ Bm,
                    const float* __restrict__ bias, float* __restrict__ C,
                    int M, int N, int K)
{
    __shared__ float As[2][GBM][LDA];
    __shared__ float Bs[2][GBK][LDB];
    __shared__ float biasS[16][LDB];

    const int tid  = threadIdx.x;
    const int wid  = tid >> 5;
    const int brow = blockIdx.y * GBM;
    const int bcol = blockIdx.x * GBN;
    const int wm   = (wid & 3) * 32;
    const int wn   = (wid >> 2) * 64;

    for (int t = 0; t < 8; t++) {
        int idx = tid + t * 256;
        biasS[idx >> 7][idx & 127] = bias[bcol + (idx & 127)];
    }
    __syncthreads();

    wmma::fragment<wmma::accumulator, 16, 16, 8, float> acc[2][4];
    #pragma unroll
    for (int i = 0; i < 2; i++)
        #pragma unroll
        for (int j = 0; j < 4; j++)
            wmma::load_matrix_sync(acc[i][j], &biasS[0][wn + j*16], LDB,
                                   wmma::mem_row_major);

    const int ar0 = tid >> 2,  ac0 = (tid & 3) << 2;
    const int br0 = tid >> 5,  bc0 = (tid & 31) << 2;

    const float* Ap0 = A  + (long)(brow + ar0) * K + ac0;
    const float* Ap1 = A  + (long)(brow + ar0 + 64) * K + ac0;
    const float* Bp0 = Bm + (long)br0 * N + bcol + bc0;
    const float* Bp1 = Bm + (long)(br0 + 8) * N + bcol + bc0;

    {
        float4 a0 = *(const float4*)Ap0;
        float4 a1 = *(const float4*)Ap1;
        float4 b0 = *(const float4*)Bp0;
        float4 b1 = *(const float4*)Bp1;
        As[0][ar0][ac0+0]=rtf32(a0.x); As[0][ar0][ac0+1]=rtf32(a0.y);
        As[0][ar0][ac0+2]=rtf32(a0.z); As[0][ar0][ac0+3]=rtf32(a0.w);
        As[0][ar0+64][ac0+0]=rtf32(a1.x); As[0][ar0+64][ac0+1]=rtf32(a1.y);
        As[0][ar0+64][ac0+2]=rtf32(a1.z); As[0][ar0+64][ac0+3]=rtf32(a1.w);
        Bs[0][br0][bc0+0]=rtf32(b0.x); Bs[0][br0][bc0+1]=rtf32(b0.y);
        Bs[0][br0][bc0+2]=rtf32(b0.z); Bs[0][br0][bc0+3]=rtf32(b0.w);
        Bs[0][br0+8][bc0+0]=rtf32(b1.x); Bs[0][br0+8][bc0+1]=rtf32(b1.y);
        Bs[0][br0+8][bc0+2]=rtf32(b1.z); Bs[0][br0+8][bc0+3]=rtf32(b1.w);
    }
    __syncthreads();

    int buf = 0;
    for (int k0 = 0; k0 < K; k0 += GBK) {
        float4 a0, a1, b0, b1;
        const bool more = (k0 + GBK) < K;
        if (more) {
            a0 = *(const float4*)(Ap0 + k0 + GBK);
            a1 = *(const float4*)(Ap1 + k0 + GBK);
            b0 = *(const float4*)(Bp0 + (long)(k0 + GBK) * N);
            b1 = *(const float4*)(Bp1 + (long)(k0 + GBK) * N);
        }

        #pragma unroll
        for (int kk = 0; kk < GBK; kk += 8) {
            wmma::fragment<wmma::matrix_a, 16, 16, 8, wmma::precision::tf32,
                           wmma::row_major> a_frag[2];
            wmma::fragment<wmma::matrix_b, 16, 16, 8, wmma::precision::tf32,
                           wmma::row_major> b_frag[4];
            #pragma unroll
            for (int i = 0; i < 2; i++)
                wmma::load_matrix_sync(a_frag[i], &As[buf][wm + i*16][kk], LDA);
            #pragma unroll
            for (int j = 0; j < 4; j++)
                wmma::load_matrix_sync(b_frag[j], &Bs[buf][kk][wn + j*16], LDB);
            #pragma unroll
            for (int i = 0; i < 2; i++)
                #pragma unroll
                for (int j = 0; j < 4; j++)
                    wmma::mma_sync(acc[i][j], a_frag[i], b_frag[j], acc[i][j]);
        }

        if (more) {
            As[buf^1][ar0][ac0+0]=rtf32(a0.x); As[buf^1][ar0][ac0+1]=rtf32(a0.y);
            As[buf^1][ar0][ac0+2]=rtf32(a0.z); As[buf^1][ar0][ac0+3]=rtf32(a0.w);
            As[buf^1][ar0+64][ac0+0]=rtf32(a1.x); As[buf^1][ar0+64][ac0+1]=rtf32(a1.y);
            As[buf^1][ar0+64][ac0+2]=rtf32(a1.z); As[buf^1][ar0+64][ac0+3]=rtf32(a1.w);
            Bs[buf^1][br0][bc0+0]=rtf32(b0.x); Bs[buf^1][br0][bc0+1]=rtf32(b0.y);
            Bs[buf^1][br0][bc0+2]=rtf32(b0.z); Bs[buf^1][br0][bc0+3]=rtf32(b0.w);
            Bs[buf^1][br0+8][bc0+0]=rtf32(b1.x); Bs[buf^1][br0+8][bc0+1]=rtf32(b1.y);
            Bs[buf^1][br0+8][bc0+2]=rtf32(b1.z); Bs[buf^1][br0+8][bc0+3]=rtf32(b1.w);
        }
        __syncthreads();
        buf ^= 1;
    }

    #pragma unroll
    for (int i = 0; i < 2; i++)
        #pragma unroll
        for (int j = 0; j < 4; j++)
            wmma::store_matrix_sync(
                C + (long)(brow + wm + i*16) * N + bcol + wn + j*16,
                acc[i][j], N, wmma::mem_row_major);
}

// ===========================================================================
// Tensor-core causal flash attention (mma.sync m16n8k8 tf32, explicit layout).
// Block: 128 threads = 4 warps; 64 queries/block (warp w owns rows w*16..+15).
// Key tiles of 64. Scores: S16x64 = Q(A) @ K^T(B). Softmax on acc registers
// (rows are known: c0,c1 -> row g; c2,c3 -> row g+8). P goes through per-warp
// smem to re-shape into A-fragment layout. O acc: 8 n-tiles of 16x8, rescaled
// per-row online.
// grid = (S/64, H, B)
// ===========================================================================
#define LDK 36
#define LDV 68
#define LDP 72

__device__ __forceinline__ void mma8(float4& d, const uint32_t* a,
                                     uint32_t b0, uint32_t b1)
{
    asm volatile(
        "mma.sync.aligned.m16n8k8.row.col.f32.tf32.tf32.f32 "
        "{%0,%1,%2,%3},{%4,%5,%6,%7},{%8,%9},{%0,%1,%2,%3};"
        : "+f"(d.x), "+f"(d.y), "+f"(d.z), "+f"(d.w)
        : "r"(a[0]), "r"(a[1]), "r"(a[2]), "r"(a[3]), "r"(b0), "r"(b1));
}

__global__ __launch_bounds__(128)
void attn_mma(const float* __restrict__ x2, float* __restrict__ ao)
{
    __shared__ float Ks[64 * LDK];
    __shared__ float Vs[64 * LDV];
    __shared__ float Ps[4 * 16 * LDP];   // per-warp P buffer (reused as Q stage)

    const int tid  = threadIdx.x;
    const int w    = tid >> 5;
    const int lane = tid & 31;
    const int g    = lane >> 2;
    const int t    = lane & 3;
    const int h    = blockIdx.y;
    const int b    = blockIdx.z;
    const int q0   = blockIdx.x * 64;

    float* Pw = Ps + w * 16 * LDP;

    // ---- stage Q [64][32] (tf32-rounded) into Ps region -------------------
    {
        const float* qb = x2 + (long)(b * S_ + q0) * NF + h * KJL;
        #pragma unroll
        for (int i = 0; i < 4; i++) {
            int idx = tid + i * 128;
            int r = idx >> 3, c = (idx & 7) << 2;
            float4 v = *(const float4*)(qb + (long)r * NF + c);
            Ps[r*32 + c + 0] = rtf32(v.x);
            Ps[r*32 + c + 1] = rtf32(v.y);
            Ps[r*32 + c + 2] = rtf32(v.z);
            Ps[r*32 + c + 3] = rtf32(v.w);
        }
    }
    __syncthreads();

    // ---- Q fragments: a0=(g,t) a1=(g+8,t) a2=(g,t+4) a3=(g+8,t+4) ---------
    uint32_t qf[4][4];
    #pragma unroll
    for (int ks = 0; ks < 4; ks++) {
        qf[ks][0] = __float_as_uint(Ps[(w*16 + g    )*32 + ks*8 + t    ]);
        qf[ks][1] = __float_as_uint(Ps[(w*16 + g + 8)*32 + ks*8 + t    ]);
        qf[ks][2] = __float_as_uint(Ps[(w*16 + g    )*32 + ks*8 + t + 4]);
        qf[ks][3] = __float_as_uint(Ps[(w*16 + g + 8)*32 + ks*8 + t + 4]);
    }

    float4 oacc[8];
    #pragma unroll
    for (int nt = 0; nt < 8; nt++) oacc[nt] = make_float4(0.f, 0.f, 0.f, 0.f);
    float m0 = -1e30f, m1 = -1e30f, l0 = 0.f, l1 = 0.f;

    const int R0 = q0 + w*16 + g;
    const int R1 = R0 + 8;
    const int nkt = blockIdx.x + 1;

    for (int kt = 0; kt < nkt; kt++) {
        // ---- load K tile [64][32] and V tile [64][64], tf32-rounded -------
        {
            const float* kb = x2 + (long)(b*S_ + kt*64) * NF + 512 + h*KJL;
            #pragma unroll
            for (int i = 0; i < 4; i++) {
                int idx = tid + i * 128;
                int r = idx >> 3, c = (idx & 7) << 2;
                float4 v = *(const float4*)(kb + (long)r * NF + c);
                Ks[r*LDK + c + 0] = rtf32(v.x);
                Ks[r*LDK + c + 1] = rtf32(v.y);
                Ks[r*LDK + c + 2] = rtf32(v.z);
                Ks[r*LDK + c + 3] = rtf32(v.w);
            }
            const float* vb = x2 + (long)(b*S_ + kt*64) * NF + 1024 + h*HD_;
            #pragma unroll
            for (int i = 0; i < 8; i++) {
                int idx = tid + i * 128;
                int r = idx >> 4, c = (idx & 15) << 2;
                float4 v = *(const float4*)(vb + (long)r * NF + c);
                Vs[r*LDV + c + 0] = rtf32(v.x);
                Vs[r*LDV + c + 1] = rtf32(v.y);
                Vs[r*LDV + c + 2] = rtf32(v.z);
                Vs[r*LDV + c + 3] = rtf32(v.w);
            }
        }
        __syncthreads();

        // ---- S = Q @ K^T : 8 n-tiles of 16x8 ------------------------------
        float4 sa[8];
        #pragma unroll
        for (int nt = 0; nt < 8; nt++) {
            sa[nt] = make_float4(0.f, 0.f, 0.f, 0.f);
            #pragma unroll
            for (int ks = 0; ks < 4; ks++) {
                uint32_t b0 = __float_as_uint(Ks[(nt*8 + g)*LDK + ks*8 + t    ]);
                uint32_t b1 = __float_as_uint(Ks[(nt*8 + g)*LDK + ks*8 + t + 4]);
                mma8(sa[nt], qf[ks], b0, b1);
            }
        }

        // ---- scale + causal mask + online softmax -------------------------
        float mx0 = -1e30f, mx1 = -1e30f;
        #pragma unroll
        for (int nt = 0; nt < 8; nt++) {
            const int c0 = kt*64 + nt*8 + 2*t;
            const int c1 = c0 + 1;
            sa[nt].x = (c0 <= R0) ? sa[nt].x * 0.125f : -1e30f;
            sa[nt].y = (c1 <= R0) ? sa[nt].y * 0.125f : -1e30f;
            sa[nt].z = (c0 <= R1) ? sa[nt].z * 0.125f : -1e30f;
            sa[nt].w = (c1 <= R1) ? sa[nt].w * 0.125f : -1e30f;
            mx0 = fmaxf(mx0, fmaxf(sa[nt].x, sa[nt].y));
            mx1 = fmaxf(mx1, fmaxf(sa[nt].z, sa[nt].w));
        }
        mx0 = fmaxf(mx0, __shfl_xor_sync(0xffffffff, mx0, 1));
        mx0 = fmaxf(mx0, __shfl_xor_sync(0xffffffff, mx0, 2));
        mx1 = fmaxf(mx1, __shfl_xor_sync(0xffffffff, mx1, 1));
        mx1 = fmaxf(mx1, __shfl_xor_sync(0xffffffff, mx1, 2));

        const float nm0 = fmaxf(m0, mx0);
        const float nm1 = fmaxf(m1, mx1);
        const float sc0 = __expf(m0 - nm0);
        const float sc1 = __expf(m1 - nm1);

        float ps0 = 0.f, ps1 = 0.f;
        #pragma unroll
        for (int nt = 0; nt < 8; nt++) {
            sa[nt].x = __expf(sa[nt].x - nm0);
            sa[nt].y = __expf(sa[nt].y - nm0);
            sa[nt].z = __expf(sa[nt].z - nm1);
            sa[nt].w = __expf(sa[nt].w - nm1);
            ps0 += sa[nt].x + sa[nt].y;
            ps1 += sa[nt].z + sa[nt].w;
        }
        ps0 += __shfl_xor_sync(0xffffffff, ps0, 1);
        ps0 += __shfl_xor_sync(0xffffffff, ps0, 2);
        ps1 += __shfl_xor_sync(0xffffffff, ps1, 1);
        ps1 += __shfl_xor_sync(0xffffffff, ps1, 2);

        l0 = l0 * sc0 + ps0;  m0 = nm0;
        l1 = l1 * sc1 + ps1;  m1 = nm1;

        #pragma unroll
        for (int nt = 0; nt < 8; nt++) {
            oacc[nt].x *= sc0;  oacc[nt].y *= sc0;
            oacc[nt].z *= sc1;  oacc[nt].w *= sc1;
        }

        // ---- store P (tf32-rounded) to per-warp smem ----------------------
        #pragma unroll
        for (int nt = 0; nt < 8; nt++) {
            float2 p0 = make_float2(rtf32(sa[nt].x), rtf32(sa[nt].y));
            float2 p1 = make_float2(rtf32(sa[nt].z), rtf32(sa[nt].w));
            *(float2*)&Pw[(g    )*LDP + nt*8 + 2*t] = p0;
            *(float2*)&Pw[(g + 8)*LDP + nt*8 + 2*t] = p1;
        }
        __syncwarp();

        // ---- O += P @ V : k over 64 keys, 8 d-tiles -----------------------
        #pragma unroll
        for (int ks = 0; ks < 8; ks++) {
            uint32_t pa[4];
            pa[0] = __float_as_uint(Pw[(g    )*LDP + ks*8 + t    ]);
            pa[1] = __float_as_uint(Pw[(g + 8)*LDP + ks*8 + t    ]);
            pa[2] = __float_as_uint(Pw[(g    )*LDP + ks*8 + t + 4]);
            pa[3] = __float_as_uint(Pw[(g + 8)*LDP + ks*8 + t + 4]);
            #pragma unroll
            for (int nt = 0; nt < 8; nt++) {
                uint32_t b0 = __float_as_uint(Vs[(ks*8 + t    )*LDV + nt*8 + g]);
                uint32_t b1 = __float_as_uint(Vs[(ks*8 + t + 4)*LDV + nt*8 + g]);
                mma8(oacc[nt], pa, b0, b1);
            }
        }
        __syncwarp();
        __syncthreads();
    }

    // ---- normalize + store ------------------------------------------------
    const float inv0 = 1.f / l0;
    const float inv1 = 1.f / l1;
    float* o0 = ao + (long)(b*S_ + R0) * D_ + h*HD_;
    float* o1 = ao + (long)(b*S_ + R1) * D_ + h*HD_;
    #pragma unroll
    for (int nt = 0; nt < 8; nt++) {
        *(float2*)(o0 + nt*8 + 2*t) = make_float2(oacc[nt].x * inv0, oacc[nt].y * inv0);
        *(float2*)(o1 + nt*8 + 2*t) = make_float2(oacc[nt].z * inv1, oacc[nt].w * inv1);
    }
}

// ===========================================================================
extern "C" void kernel_launch(void* const* d_in, const int* in_sizes, int n_in,
                              void* d_out, int out_size)
{
    const float* X    = (const float*)d_in[0];
    const float* Wat  = (const float*)d_in[1];
    const float* bat  = (const float*)d_in[2];
    const float* Sp   = (const float*)d_in[3];
    const float* Wp   = (const float*)d_in[4];
    const float* bp   = (const float*)d_in[5];
    float* out = (float*)d_out;

    float *wf, *bf, *x2, *ao;
    cudaGetSymbolAddress((void**)&wf, g_wf);
    cudaGetSymbolAddress((void**)&bf, g_bf);
    cudaGetSymbolAddress((void**)&x2, g_x2);
    cudaGetSymbolAddress((void**)&ao, g_ao);

    fold_weights<<<D_, 256>>>(Wat, Sp, wf);
    fold_bias<<<NF/256, 256>>>(bat, Sp, bf);

    dim3 g1(NF/GBN, M_/GBM);
    tf32_gemm_bias<<<g1, 256>>>(X, wf, bf, x2, M_, NF, D_);

    dim3 g3(S_/64, H_, B_);
    attn_mma<<<g3, 128>>>(x2, ao);

    dim3 g4(D_/GBN, M_/GBM);
    tf32_gemm_bias<<<g4, 256>>>(ao, Wp, bp, out, M_, D_, D_);
}